// round 15
// baseline (speedup 1.0000x reference)
#include <cuda_runtime.h>
#include <cuda_bf16.h>
#include <cuda_fp16.h>
#include <math.h>
#include <stdint.h>

// ---------------- model constants ----------------
#define BS    64
#define T_    96
#define C_    16
#define IN_   16
#define H_    256
#define NH_   8
#define DH_   32
#define NCLS  4
#define L_    100          // T + NCLS
#define LAYERS 4
#define BP    (BS * C_)    // 1024 sequences
#define ROWS  (BP * L_)    // 102400 token rows
#define EPS_  1e-5f

// ================= low-level helpers =================
__device__ __forceinline__ uint32_t smem_u32(const void* p) {
    uint32_t a;
    asm("{ .reg .u64 t; cvta.to.shared.u64 t, %1; cvt.u32.u64 %0, t; }"
        : "=r"(a) : "l"(p));
    return a;
}
__device__ __forceinline__ void cp16(uint32_t dst, const void* src) {
    asm volatile("cp.async.cg.shared.global [%0], [%1], 16;" :: "r"(dst), "l"(src) : "memory");
}
__device__ __forceinline__ void ldsm4(uint32_t* r, uint32_t addr) {
    asm volatile("ldmatrix.sync.aligned.m8n8.x4.shared.b16 {%0,%1,%2,%3}, [%4];"
        : "=r"(r[0]), "=r"(r[1]), "=r"(r[2]), "=r"(r[3]) : "r"(addr));
}
__device__ __forceinline__ void ldsm2(uint32_t* r, uint32_t addr) {
    asm volatile("ldmatrix.sync.aligned.m8n8.x2.shared.b16 {%0,%1}, [%2];"
        : "=r"(r[0]), "=r"(r[1]) : "r"(addr));
}
// fp16 MMA, fp32 accumulate
__device__ __forceinline__ void mma16816h(float* d, const uint32_t* a, const uint32_t* b) {
    asm volatile("mma.sync.aligned.m16n8k16.row.col.f32.f16.f16.f32 "
        "{%0,%1,%2,%3}, {%4,%5,%6,%7}, {%8,%9}, {%0,%1,%2,%3};"
        : "+f"(d[0]), "+f"(d[1]), "+f"(d[2]), "+f"(d[3])
        : "r"(a[0]), "r"(a[1]), "r"(a[2]), "r"(a[3]), "r"(b[0]), "r"(b[1]));
}

// ---------------- fp16 split helper ----------------
__device__ __forceinline__ void split_fp16(float v, __half& hi, __half& lo) {
    hi = __float2half_rn(v);
    lo = __float2half_rn(v - __half2float(hi));
}

// ---------------- scratch (device globals) -------------
__device__ __align__(256) float  g_h  [(size_t)ROWS * H_];
__device__ __align__(256) __half g_hh [(size_t)ROWS * H_];          // A: encoder input
__device__ __align__(256) __half g_qkv[(size_t)ROWS * 3 * H_];
__device__ __align__(256) __half g_a  [(size_t)ROWS * H_];          // A: attention out
__device__ __align__(256) float  g_t1 [(size_t)ROWS * H_];
__device__ __align__(256) __half g_f1 [(size_t)ROWS * 4 * H_];      // A: relu out
// weights (fp16 pairs)
__device__ __align__(256) __half g_wqkvh[LAYERS * 3 * H_ * H_], g_wqkvl[LAYERS * 3 * H_ * H_];
__device__ __align__(256) __half g_woh  [LAYERS * H_ * H_],     g_wol  [LAYERS * H_ * H_];
__device__ __align__(256) __half g_w1h  [LAYERS * 4 * H_ * H_], g_w1l  [LAYERS * 4 * H_ * H_];
__device__ __align__(256) __half g_w2h  [LAYERS * 4 * H_ * H_], g_w2l  [LAYERS * 4 * H_ * H_];
__device__ __align__(256) __half g_wmh  [(LAYERS-1) * H_ * 3 * H_], g_wml[(LAYERS-1) * H_ * 3 * H_];
// graph / mixprop
__device__ float g_m1 [C_ * H_];
__device__ float g_m2 [C_ * H_];
__device__ float g_adj[C_ * C_];
__device__ __align__(256) __half g_ho [(size_t)BS * C_ * NCLS * 3 * H_];   // A: mixprop concat
__device__ __align__(256) float  g_mpo[(size_t)BS * C_ * NCLS * H_];
__device__ __align__(256) float  g_z  [(size_t)BS * C_ * NCLS * H_];
__device__ float g_d1 [BS * H_];

// ================= HMMA GEMM (fp16x2, 128x64 tile, 3 CTAs/SM) =============
// C[M,N] = A[M,K] @ B[N,K]^T + bias.
// mode 0: fp32 out; mode 1: relu + fp16 single; mode 2: fp16 out (Cf cast).
// grid = (N/64, M/128), 256 threads (8 warps: 4 m-warps x 2 n-warps,
// warp tile 32x64... no: warp tile 32 rows x 32 cols). M %128, N %64, K %32.
#define ASTR    40                        // fp16 row pitch (80B) — conflict-free
#define A_TILE  (128 * ASTR * 2)          // 10240 bytes
#define B_TILE  (64 * ASTR * 2)           // 5120 bytes
#define STAGE_B (A_TILE + 2 * B_TILE)     // 20480
#define SMEM_GEMM_BYTES (2 * STAGE_B)     // 40960
#define OFF_A   0
#define OFF_BH  A_TILE
#define OFF_BL  (A_TILE + B_TILE)

__global__ __launch_bounds__(256, 3) void gemm_h2_kernel(
    const __half* __restrict__ A,
    const __half* __restrict__ Bh, const __half* __restrict__ Bl,
    const float* __restrict__ bias,
    float* __restrict__ Cf, __half* __restrict__ Ch,
    int M, int N, int K, int mode)
{
    extern __shared__ char smem[];
    uint32_t sb = smem_u32(smem);
    int tid = threadIdx.x;
    int lane = tid & 31;
    int w = tid >> 5;
    int wm = w >> 1;            // 0..3 (32-row slice)
    int wn = w & 1;             // 0..1 (32-col slice)
    int m0 = blockIdx.y * 128, n0 = blockIdx.x * 64;

    float acc[2][4][4];
    #pragma unroll
    for (int i = 0; i < 2; i++)
        #pragma unroll
        for (int j = 0; j < 4; j++)
            #pragma unroll
            for (int k = 0; k < 4; k++) acc[i][j][k] = 0.f;

    int nch = K >> 5;

    // ---- stage loader: A 128x32 (2 cp16/thr), Bh/Bl 64x32 (1 cp16/thr) ----
    #define ISSUE_STAGE(cidx) do {                                               \
        int _s = (cidx) & 1; int _kc = (cidx) << 5;                              \
        uint32_t _base = sb + _s * STAGE_B;                                      \
        _Pragma("unroll")                                                        \
        for (int _i = 0; _i < 2; _i++) {                                         \
            int _id = tid + _i * 256;                                            \
            int _r = _id >> 2;                                                   \
            int _cc = (_id & 3) << 3;                                            \
            uint32_t _do = (uint32_t)(_r * (ASTR * 2) + _cc * 2);                \
            size_t _ga = (size_t)(m0 + _r) * K + _kc + _cc;                      \
            cp16(_base + OFF_A + _do, A + _ga);                                  \
        }                                                                        \
        {                                                                        \
            int _r = tid >> 2;                                                   \
            int _cc = (tid & 3) << 3;                                            \
            uint32_t _do = (uint32_t)(_r * (ASTR * 2) + _cc * 2);                \
            size_t _gb = (size_t)(n0 + _r) * K + _kc + _cc;                      \
            cp16(_base + OFF_BH + _do, Bh + _gb);                                \
            cp16(_base + OFF_BL + _do, Bl + _gb);                                \
        }                                                                        \
        asm volatile("cp.async.commit_group;" ::: "memory");                     \
    } while (0)

    ISSUE_STAGE(0);

    for (int c = 0; c < nch; c++) {
        if (c + 1 < nch) {
            ISSUE_STAGE(c + 1);
            asm volatile("cp.async.wait_group 1;" ::: "memory");
        } else {
            asm volatile("cp.async.wait_group 0;" ::: "memory");
        }
        __syncthreads();

        uint32_t base = sb + (c & 1) * STAGE_B;
        #pragma unroll
        for (int ks = 0; ks < 2; ks++) {
            uint32_t ah[2][4], bh[4][2], bl[4][2];
            int arow = wm * 32 + (lane & 15);
            int akc  = ks * 16 + (lane >> 4) * 8;
            #pragma unroll
            for (int mf = 0; mf < 2; mf++) {
                uint32_t off = (uint32_t)(((arow + mf * 16) * ASTR + akc) * 2);
                ldsm4(ah[mf], base + OFF_A + off);
            }
            int brow = wn * 32 + (lane & 7);
            int bkc  = ks * 16 + (((lane & 15) >> 3)) * 8;
            #pragma unroll
            for (int nf = 0; nf < 4; nf++) {
                uint32_t off = (uint32_t)(((brow + nf * 8) * ASTR + bkc) * 2);
                ldsm2(bh[nf], base + OFF_BH + off);
                ldsm2(bl[nf], base + OFF_BL + off);
            }
            #pragma unroll
            for (int mf = 0; mf < 2; mf++)
                #pragma unroll
                for (int nf = 0; nf < 4; nf++) {
                    mma16816h(acc[mf][nf], ah[mf], bh[nf]);
                    mma16816h(acc[mf][nf], ah[mf], bl[nf]);
                }
        }
        __syncthreads();
    }

    // ---- epilogue ----
    int rbase = m0 + wm * 32 + (lane >> 2);
    int cbase = n0 + wn * 32 + (lane & 3) * 2;
    #pragma unroll
    for (int mf = 0; mf < 2; mf++) {
        #pragma unroll
        for (int nf = 0; nf < 4; nf++) {
            int r = rbase + mf * 16;
            int cc = cbase + nf * 8;
            float b0 = bias[cc], b1 = bias[cc + 1];
            float v0 = acc[mf][nf][0] + b0, v1 = acc[mf][nf][1] + b1;
            float v2 = acc[mf][nf][2] + b0, v3 = acc[mf][nf][3] + b1;
            if (mode == 0) {
                *(float2*)(Cf + (size_t)r * N + cc)       = make_float2(v0, v1);
                *(float2*)(Cf + (size_t)(r + 8) * N + cc) = make_float2(v2, v3);
            } else if (mode == 2) {
                __half* Hc = (__half*)Cf;
                *(__half2*)(Hc + (size_t)r * N + cc)       = __floats2half2_rn(v0, v1);
                *(__half2*)(Hc + (size_t)(r + 8) * N + cc) = __floats2half2_rn(v2, v3);
            } else {
                v0 = fmaxf(v0, 0.f); v1 = fmaxf(v1, 0.f);
                v2 = fmaxf(v2, 0.f); v3 = fmaxf(v3, 0.f);
                *(__half2*)(Ch + (size_t)r * N + cc)       = __floats2half2_rn(v0, v1);
                *(__half2*)(Ch + (size_t)(r + 8) * N + cc) = __floats2half2_rn(v2, v3);
            }
        }
    }
}

// ================= misc kernels =================
// merged weight conversion (float4-vectorized, 5 segments) -> fp16 pairs
#define NWQKV (LAYERS * 3 * H_ * H_)
#define NWO   (LAYERS * H_ * H_)
#define NW1   (LAYERS * 4 * H_ * H_)
#define NW2   (LAYERS * 4 * H_ * H_)
#define NWM   ((LAYERS - 1) * H_ * 3 * H_)
#define NCONV ((NWQKV + NWO + NW1 + NW2 + NWM) / 4)

__global__ __launch_bounds__(256) void conv_all_kernel(
    const float* __restrict__ Wqkv, const float* __restrict__ Wo,
    const float* __restrict__ W1,   const float* __restrict__ W2,
    const float* __restrict__ Wm)
{
    int i4 = blockIdx.x * 256 + threadIdx.x;
    if (i4 >= NCONV) return;
    int i = i4 * 4;
    const float* src; __half *hi, *lo; int off;
    if (i < NWQKV) { src = Wqkv; hi = g_wqkvh; lo = g_wqkvl; off = i; }
    else if (i < NWQKV + NWO) { src = Wo; hi = g_woh; lo = g_wol; off = i - NWQKV; }
    else if (i < NWQKV + NWO + NW1) { src = W1; hi = g_w1h; lo = g_w1l; off = i - NWQKV - NWO; }
    else if (i < NWQKV + NWO + NW1 + NW2) { src = W2; hi = g_w2h; lo = g_w2l; off = i - NWQKV - NWO - NW1; }
    else { src = Wm; hi = g_wmh; lo = g_wml; off = i - NWQKV - NWO - NW1 - NW2; }
    float4 v = *(const float4*)(src + off);
    __half h0, l0, h1, l1, h2, l2, h3, l3;
    split_fp16(v.x, h0, l0); split_fp16(v.y, h1, l1);
    split_fp16(v.z, h2, l2); split_fp16(v.w, h3, l3);
    __half2 p0; p0.x = h0; p0.y = h1;
    __half2 p1; p1.x = h2; p1.y = h3;
    __half2 q0; q0.x = l0; q0.y = l1;
    __half2 q1; q1.x = l2; q1.y = l3;
    *(__half2*)(hi + off)     = p0;
    *(__half2*)(hi + off + 2) = p1;
    *(__half2*)(lo + off)     = q0;
    *(__half2*)(lo + off + 2) = q1;
}

__global__ __launch_bounds__(256) void embed_kernel(
    const float* __restrict__ x, const float* __restrict__ Wfc,
    const float* __restrict__ bfc, const float* __restrict__ cls,
    const float* __restrict__ pos)
{
    int row = blockIdx.x;
    int l  = row % L_;
    int bc = row / L_;
    int c  = bc % C_;
    int b  = bc / C_;
    int t  = threadIdx.x;

    __shared__ float xs[IN_];
    float val;
    if (l < T_) {
        if (t < IN_) xs[t] = x[(((size_t)b * T_ + l) * C_ + c) * IN_ + t];
        __syncthreads();
        float s = bfc[t];
        #pragma unroll
        for (int i = 0; i < IN_; i++) s += xs[i] * Wfc[t * IN_ + i];
        val = s;
    } else {
        val = cls[((l - T_) * C_ + c) * H_ + t];
    }
    val += pos[((size_t)l * C_ + c) * H_ + t];
    size_t o = (size_t)row * H_ + t;
    g_h[o]  = val;
    g_hh[o] = __float2half_rn(val);
}

__global__ __launch_bounds__(256) void graph_kernel(
    const float* __restrict__ emb1, const float* __restrict__ emb2,
    const float* __restrict__ Wl1, const float* __restrict__ bl1,
    const float* __restrict__ Wl2, const float* __restrict__ bl2)
{
    int t = threadIdx.x;
    for (int i = 0; i < C_; i++) {
        float s1 = bl1[t], s2 = bl2[t];
        for (int k = 0; k < H_; k++) {
            s1 += emb1[i * H_ + k] * Wl1[t * H_ + k];
            s2 += emb2[i * H_ + k] * Wl2[t * H_ + k];
        }
        g_m1[i * H_ + t] = tanhf(s1);
        g_m2[i * H_ + t] = tanhf(s2);
    }
    __syncthreads();

    __shared__ float adj[C_][C_];
    __shared__ float rsum[C_];
    int v = t >> 4, w = t & 15;
    float s = 0.f;
    for (int j = 0; j < H_; j++)
        s += g_m1[v * H_ + j] * g_m2[w * H_ + j]
           - g_m2[v * H_ + j] * g_m1[w * H_ + j];
    float gv = fmaxf(tanhf(s), 0.f);
    if (v == w) gv += 1.0f;
    adj[v][w] = gv;
    __syncthreads();
    if (t < C_) {
        float r = 0.f;
        for (int k = 0; k < C_; k++) r += adj[t][k];
        rsum[t] = r;
    }
    __syncthreads();
    g_adj[t] = adj[v][w] / rsum[v];
}

// ================= attention (online softmax, fp16 qkv, fp16 out) ==========
__global__ __launch_bounds__(128) void attn_kernel(const __half* __restrict__ qkv)
{
    int bh = blockIdx.x;
    int b = bh >> 3;
    int h = bh & 7;
    __shared__ float4 Ks[L_][8];
    __shared__ float4 Vs[L_][8];
    const __half* base = qkv + (size_t)b * L_ * (3 * H_) + h * DH_;
    for (int idx = threadIdx.x; idx < L_ * 8; idx += 128) {
        int l = idx >> 3, k4 = idx & 7;
        const __half2* kp = (const __half2*)(base + (size_t)l * (3 * H_) + H_     + k4 * 4);
        const __half2* vp = (const __half2*)(base + (size_t)l * (3 * H_) + 2 * H_ + k4 * 4);
        float2 k0 = __half22float2(kp[0]), k1 = __half22float2(kp[1]);
        float2 vv0 = __half22float2(vp[0]), vv1 = __half22float2(vp[1]);
        Ks[l][k4] = make_float4(k0.x, k0.y, k1.x, k1.y);
        Vs[l][k4] = make_float4(vv0.x, vv0.y, vv1.x, vv1.y);
    }
    __syncthreads();

    int i = threadIdx.x;
    if (i < L_) {
        float4 q[8];
        #pragma unroll
        for (int k4 = 0; k4 < 8; k4++) {
            const __half2* qp = (const __half2*)(base + (size_t)i * (3 * H_) + k4 * 4);
            float2 q0 = __half22float2(qp[0]), q1 = __half22float2(qp[1]);
            q[k4] = make_float4(q0.x, q0.y, q1.x, q1.y);
        }

        float m = -1e30f, lsum = 0.f;
        float4 acc[8];
        #pragma unroll
        for (int k4 = 0; k4 < 8; k4++) acc[k4] = make_float4(0.f, 0.f, 0.f, 0.f);

        int jmax = (i >= T_) ? L_ : (i + 1);
        for (int j = 0; j < jmax; j++) {
            float a0 = 0.f, a1 = 0.f, a2 = 0.f, a3 = 0.f;
            #pragma unroll
            for (int k4 = 0; k4 < 8; k4++) {
                float4 kv = Ks[j][k4];
                a0 += q[k4].x * kv.x;
                a1 += q[k4].y * kv.y;
                a2 += q[k4].z * kv.z;
                a3 += q[k4].w * kv.w;
            }
            float s = ((a0 + a1) + (a2 + a3)) * 0.17677669529663687f;
            if (s <= m) {
                float p = __expf(s - m);
                lsum += p;
                #pragma unroll
                for (int k4 = 0; k4 < 8; k4++) {
                    float4 vv = Vs[j][k4];
                    acc[k4].x += p * vv.x;
                    acc[k4].y += p * vv.y;
                    acc[k4].z += p * vv.z;
                    acc[k4].w += p * vv.w;
                }
            } else {
                float sc = __expf(m - s);
                lsum = lsum * sc + 1.f;
                #pragma unroll
                for (int k4 = 0; k4 < 8; k4++) {
                    float4 vv = Vs[j][k4];
                    acc[k4].x = acc[k4].x * sc + vv.x;
                    acc[k4].y = acc[k4].y * sc + vv.y;
                    acc[k4].z = acc[k4].z * sc + vv.z;
                    acc[k4].w = acc[k4].w * sc + vv.w;
                }
                m = s;
            }
        }
        float inv = 1.f / lsum;
        size_t o = ((size_t)b * L_ + i) * H_ + h * DH_;
        #pragma unroll
        for (int k4 = 0; k4 < 8; k4++) {
            *(__half2*)(g_a + o + k4 * 4)     = __floats2half2_rn(acc[k4].x * inv, acc[k4].y * inv);
            *(__half2*)(g_a + o + k4 * 4 + 2) = __floats2half2_rn(acc[k4].z * inv, acc[k4].w * inv);
        }
    }
}

// fused residual-add + LayerNorm; writes fp32 h and fp16 single
__global__ __launch_bounds__(256) void add_ln_kernel(
    const float* __restrict__ xin,
    const float* __restrict__ g, const float* __restrict__ bt)
{
    int row = blockIdx.x, t = threadIdx.x;
    size_t base = (size_t)row * H_;
    float v = g_h[base + t] + xin[base + t];

    __shared__ float ws[8];
    float s = v;
    #pragma unroll
    for (int o = 16; o > 0; o >>= 1) s += __shfl_xor_sync(0xffffffffu, s, o);
    if ((t & 31) == 0) ws[t >> 5] = s;
    __syncthreads();
    float tot = 0.f;
    #pragma unroll
    for (int i = 0; i < 8; i++) tot += ws[i];
    float mean = tot * (1.0f / H_);
    float d = v - mean;
    __syncthreads();

    float q = d * d;
    #pragma unroll
    for (int o = 16; o > 0; o >>= 1) q += __shfl_xor_sync(0xffffffffu, q, o);
    if ((t & 31) == 0) ws[t >> 5] = q;
    __syncthreads();
    float qt = 0.f;
    #pragma unroll
    for (int i = 0; i < 8; i++) qt += ws[i];
    float var = qt * (1.0f / H_);

    float out = d * rsqrtf(var + EPS_) * g[t] + bt[t];
    g_h[base + t]  = out;
    g_hh[base + t] = __float2half_rn(out);
}

// ---------------- fused mixprop (gather + 2 prop depths + fp16 out) --------
__global__ __launch_bounds__(256) void mp_fused_kernel()
{
    __shared__ float s0[C_ * H_];
    __shared__ float s1[C_ * H_];
    __shared__ float adjs[C_ * C_];

    int n = blockIdx.x >> 2;
    int l = blockIdx.x & 3;
    int t = threadIdx.x;
    adjs[t] = g_adj[t];

    #pragma unroll
    for (int w = 0; w < C_; w++) {
        float v = g_h[(((size_t)(n * C_ + w)) * L_ + T_ + l) * H_ + t];
        s0[w * H_ + t] = v;
        size_t r = (size_t)((n * C_ + w) * NCLS + l) * (3 * H_);
        g_ho[r + t] = __float2half_rn(v);
    }
    __syncthreads();

    #pragma unroll
    for (int v = 0; v < C_; v++) {
        float s = 0.f;
        #pragma unroll
        for (int w = 0; w < C_; w++)
            s += adjs[v * C_ + w] * s0[w * H_ + t];
        s1[v * H_ + t] = s;
        size_t r = (size_t)((n * C_ + v) * NCLS + l) * (3 * H_) + H_;
        g_ho[r + t] = __float2half_rn(s);
    }
    __syncthreads();

    #pragma unroll
    for (int v = 0; v < C_; v++) {
        float s = 0.f;
        #pragma unroll
        for (int w = 0; w < C_; w++)
            s += adjs[v * C_ + w] * s1[w * H_ + t];
        size_t r = (size_t)((n * C_ + v) * NCLS + l) * (3 * H_) + 2 * H_;
        g_ho[r + t] = __float2half_rn(s);
    }
}

__global__ __launch_bounds__(256) void mp_scatter_kernel()
{
    int idx = blockIdx.x * 256 + threadIdx.x;
    int o  = idx & 255;
    int r  = idx >> 8;
    int l  = r & 3;
    int nw = r >> 2;
    float v = g_mpo[(size_t)r * H_ + o];
    size_t dst = ((size_t)nw * L_ + T_ + l) * H_ + o;
    g_h[dst]  = v;
    g_hh[dst] = __float2half_rn(v);
}

// ---------------- head ----------------
__global__ __launch_bounds__(256) void tanh_gather_kernel()
{
    int idx = blockIdx.x * 256 + threadIdx.x;
    int hd = idx & 255;
    int r  = idx >> 8;
    int n  = r & 3;
    int c  = (r >> 2) & 15;
    int b  = r >> 6;
    g_z[idx] = tanhf(g_h[(((size_t)(b * C_ + c)) * L_ + T_ + n) * H_ + hd]);
}

__global__ __launch_bounds__(512) void head_gemm_kernel(
    const float* __restrict__ Wd1, const float* __restrict__ bd1)
{
    extern __shared__ float zs[];
    int b = blockIdx.x;
    int tid = threadIdx.x;
    for (int i = tid; i < C_ * NCLS * H_; i += 512)
        zs[i] = g_z[(size_t)b * (C_ * NCLS * H_) + i];
    __syncthreads();
    int wid = tid >> 5, lane = tid & 31;
    for (int o = wid; o < H_; o += 16) {
        const float* w = Wd1 + (size_t)o * (C_ * NCLS * H_);
        float s = 0.f;
        for (int k = lane; k < C_ * NCLS * H_; k += 32)
            s += zs[k] * w[k];
        #pragma unroll
        for (int off = 16; off > 0; off >>= 1)
            s += __shfl_xor_sync(0xffffffffu, s, off);
        if (lane == 0) g_d1[b * H_ + o] = s + bd1[o];
    }
}

__global__ __launch_bounds__(256) void head_kernel(
    const float* __restrict__ Wd2, const float* __restrict__ bd2,
    float* __restrict__ out)
{
    int b = blockIdx.x, t = threadIdx.x;
    float x = g_d1[b * H_ + t];
    float gl = 0.5f * x * (1.0f + erff(x * 0.70710678118654752f));
    float v = gl * Wd2[t];
    #pragma unroll
    for (int o = 16; o > 0; o >>= 1) v += __shfl_xor_sync(0xffffffffu, v, o);
    __shared__ float ws[8];
    if ((t & 31) == 0) ws[t >> 5] = v;
    __syncthreads();
    if (t == 0) {
        float s = 0.f;
        #pragma unroll
        for (int i = 0; i < 8; i++) s += ws[i];
        out[b] = s + bd2[0];
    }
}

// ---------------- host ----------------
static float* dev_ptr(const void* symbol)
{
    void* p = nullptr;
    cudaGetSymbolAddress(&p, symbol);
    return (float*)p;
}
static __half* dev_ptr_h(const void* symbol)
{
    void* p = nullptr;
    cudaGetSymbolAddress(&p, symbol);
    return (__half*)p;
}

extern "C" void kernel_launch(void* const* d_in, const int* in_sizes, int n_in,
                              void* d_out, int out_size)
{
    const float* x        = (const float*)d_in[0];
    const float* Wfc      = (const float*)d_in[3];
    const float* bfc      = (const float*)d_in[4];
    const float* cls_tok  = (const float*)d_in[5];
    const float* pos_emb  = (const float*)d_in[6];
    const float* emb1     = (const float*)d_in[7];
    const float* emb2     = (const float*)d_in[8];
    const float* Wl1      = (const float*)d_in[9];
    const float* bl1      = (const float*)d_in[10];
    const float* Wl2      = (const float*)d_in[11];
    const float* bl2      = (const float*)d_in[12];
    const float* Wqkv     = (const float*)d_in[13];
    const float* bqkv     = (const float*)d_in[14];
    const float* Wo       = (const float*)d_in[15];
    const float* bo       = (const float*)d_in[16];
    const float* W1       = (const float*)d_in[17];
    const float* b1       = (const float*)d_in[18];
    const float* W2       = (const float*)d_in[19];
    const float* b2       = (const float*)d_in[20];
    const float* ln1g     = (const float*)d_in[21];
    const float* ln1b     = (const float*)d_in[22];
    const float* ln2g     = (const float*)d_in[23];
    const float* ln2b     = (const float*)d_in[24];
    const float* Wmlp     = (const float*)d_in[25];
    const float* bmlp     = (const float*)d_in[26];
    const float* Wd1      = (const float*)d_in[27];
    const float* bd1      = (const float*)d_in[28];
    const float* Wd2      = (const float*)d_in[29];
    const float* bd2      = (const float*)d_in[30];
    float* out = (float*)d_out;

    static bool inited = false;
    static float *p_t1, *p_mpo;
    static __half *p_qkv, *p_hh, *p_a, *p_f1, *p_ho;
    static __half *p_wqkvh, *p_wqkvl, *p_woh, *p_wol, *p_w1h, *p_w1l,
                  *p_w2h, *p_w2l, *p_wmh, *p_wml;
    if (!inited) {
        cudaFuncSetAttribute(gemm_h2_kernel,
            cudaFuncAttributeMaxDynamicSharedMemorySize, SMEM_GEMM_BYTES);
        cudaFuncSetAttribute(head_gemm_kernel,
            cudaFuncAttributeMaxDynamicSharedMemorySize, C_ * NCLS * H_ * 4);
        p_t1 = dev_ptr(g_t1); p_mpo = dev_ptr(g_mpo);
        p_qkv = dev_ptr_h(g_qkv);
        p_hh = dev_ptr_h(g_hh); p_a = dev_ptr_h(g_a);
        p_f1 = dev_ptr_h(g_f1); p_ho = dev_ptr_h(g_ho);
        p_wqkvh = dev_ptr_h(g_wqkvh); p_wqkvl = dev_ptr_h(g_wqkvl);
        p_woh = dev_ptr_h(g_woh); p_wol = dev_ptr_h(g_wol);
        p_w1h = dev_ptr_h(g_w1h); p_w1l = dev_ptr_h(g_w1l);
        p_w2h = dev_ptr_h(g_w2h); p_w2l = dev_ptr_h(g_w2l);
        p_wmh = dev_ptr_h(g_wmh); p_wml = dev_ptr_h(g_wml);
        inited = true;
    }

    // launch 0: merged weight conversion
    conv_all_kernel<<<(NCONV + 255) / 256, 256>>>(Wqkv, Wo, W1, W2, Wmlp);
    // launches 1-2
    graph_kernel<<<1, 256>>>(emb1, emb2, Wl1, bl1, Wl2, bl2);
    embed_kernel<<<ROWS, 256>>>(x, Wfc, bfc, cls_tok, pos_emb);

    const int MP_THREADS = BS * C_ * NCLS * H_;   // 1,048,576

    for (int l = 0; l < LAYERS; l++) {
        if (l > 0) {
            mp_fused_kernel<<<BS * NCLS, 256>>>();
            gemm_h2_kernel<<<dim3(4, 32), 256, SMEM_GEMM_BYTES>>>(
                p_ho,
                p_wmh + (size_t)(l - 1) * H_ * 3 * H_, p_wml + (size_t)(l - 1) * H_ * 3 * H_,
                bmlp + (size_t)(l - 1) * H_,
                p_mpo, nullptr,
                BS * C_ * NCLS, H_, 3 * H_, 0);
            mp_scatter_kernel<<<MP_THREADS / 256, 256>>>();
        }

        // QKV projection -> fp16
        gemm_h2_kernel<<<dim3(12, ROWS / 128), 256, SMEM_GEMM_BYTES>>>(
            p_hh,
            p_wqkvh + (size_t)l * 3 * H_ * H_, p_wqkvl + (size_t)l * 3 * H_ * H_,
            bqkv + (size_t)l * 3 * H_,
            (float*)p_qkv, nullptr, ROWS, 3 * H_, H_, 2);

        attn_kernel<<<BP * NH_, 128>>>(p_qkv);

        // output projection -> g_t1
        gemm_h2_kernel<<<dim3(4, ROWS / 128), 256, SMEM_GEMM_BYTES>>>(
            p_a,
            p_woh + (size_t)l * H_ * H_, p_wol + (size_t)l * H_ * H_,
            bo + (size_t)l * H_,
            p_t1, nullptr, ROWS, H_, H_, 0);

        add_ln_kernel<<<ROWS, 256>>>(p_t1, ln1g + l * H_, ln1b + l * H_);

        // FFN
        gemm_h2_kernel<<<dim3(16, ROWS / 128), 256, SMEM_GEMM_BYTES>>>(
            p_hh,
            p_w1h + (size_t)l * 4 * H_ * H_, p_w1l + (size_t)l * 4 * H_ * H_,
            b1 + (size_t)l * 4 * H_,
            nullptr, p_f1, ROWS, 4 * H_, H_, 1);

        gemm_h2_kernel<<<dim3(4, ROWS / 128), 256, SMEM_GEMM_BYTES>>>(
            p_f1,
            p_w2h + (size_t)l * 4 * H_ * H_, p_w2l + (size_t)l * 4 * H_ * H_,
            b2 + (size_t)l * H_,
            p_t1, nullptr, ROWS, H_, 4 * H_, 0);

        add_ln_kernel<<<ROWS, 256>>>(p_t1, ln2g + l * H_, ln2b + l * H_);
    }

    tanh_gather_kernel<<<MP_THREADS / 256, 256>>>();
    head_gemm_kernel<<<BS, 512, C_ * NCLS * H_ * 4>>>(Wd1, bd1);
    head_kernel<<<BS, 256>>>(Wd2, bd2, out);
}

// round 16
// speedup vs baseline: 1.0330x; 1.0330x over previous
#include <cuda_runtime.h>
#include <cuda_bf16.h>
#include <cuda_fp16.h>
#include <math.h>
#include <stdint.h>

// ---------------- model constants ----------------
#define BS    64
#define T_    96
#define C_    16
#define IN_   16
#define H_    256
#define NH_   8
#define DH_   32
#define NCLS  4
#define L_    100          // T + NCLS
#define LAYERS 4
#define BP    (BS * C_)    // 1024 sequences
#define ROWS  (BP * L_)    // 102400 token rows
#define EPS_  1e-5f

// ================= low-level helpers =================
__device__ __forceinline__ uint32_t smem_u32(const void* p) {
    uint32_t a;
    asm("{ .reg .u64 t; cvta.to.shared.u64 t, %1; cvt.u32.u64 %0, t; }"
        : "=r"(a) : "l"(p));
    return a;
}
__device__ __forceinline__ void cp16(uint32_t dst, const void* src) {
    asm volatile("cp.async.cg.shared.global [%0], [%1], 16;" :: "r"(dst), "l"(src) : "memory");
}
__device__ __forceinline__ void ldsm4(uint32_t* r, uint32_t addr) {
    asm volatile("ldmatrix.sync.aligned.m8n8.x4.shared.b16 {%0,%1,%2,%3}, [%4];"
        : "=r"(r[0]), "=r"(r[1]), "=r"(r[2]), "=r"(r[3]) : "r"(addr));
}
__device__ __forceinline__ void ldsm2(uint32_t* r, uint32_t addr) {
    asm volatile("ldmatrix.sync.aligned.m8n8.x2.shared.b16 {%0,%1}, [%2];"
        : "=r"(r[0]), "=r"(r[1]) : "r"(addr));
}
// fp16 MMA, fp32 accumulate
__device__ __forceinline__ void mma16816h(float* d, const uint32_t* a, const uint32_t* b) {
    asm volatile("mma.sync.aligned.m16n8k16.row.col.f32.f16.f16.f32 "
        "{%0,%1,%2,%3}, {%4,%5,%6,%7}, {%8,%9}, {%0,%1,%2,%3};"
        : "+f"(d[0]), "+f"(d[1]), "+f"(d[2]), "+f"(d[3])
        : "r"(a[0]), "r"(a[1]), "r"(a[2]), "r"(a[3]), "r"(b[0]), "r"(b[1]));
}

// ---------------- fp16 split helper ----------------
__device__ __forceinline__ void split_fp16(float v, __half& hi, __half& lo) {
    hi = __float2half_rn(v);
    lo = __float2half_rn(v - __half2float(hi));
}

// ---------------- scratch (device globals) -------------
__device__ __align__(256) float  g_h  [(size_t)ROWS * H_];
__device__ __align__(256) __half g_hh [(size_t)ROWS * H_];          // A: encoder input
__device__ __align__(256) __half g_qkv[(size_t)ROWS * 3 * H_];
__device__ __align__(256) __half g_a  [(size_t)ROWS * H_];          // A: attention out
__device__ __align__(256) float  g_t1 [(size_t)ROWS * H_];
__device__ __align__(256) __half g_f1 [(size_t)ROWS * 4 * H_];      // A: relu out
// weights (fp16 pairs)
__device__ __align__(256) __half g_wqkvh[LAYERS * 3 * H_ * H_], g_wqkvl[LAYERS * 3 * H_ * H_];
__device__ __align__(256) __half g_woh  [LAYERS * H_ * H_],     g_wol  [LAYERS * H_ * H_];
__device__ __align__(256) __half g_w1h  [LAYERS * 4 * H_ * H_], g_w1l  [LAYERS * 4 * H_ * H_];
__device__ __align__(256) __half g_w2h  [LAYERS * 4 * H_ * H_], g_w2l  [LAYERS * 4 * H_ * H_];
__device__ __align__(256) __half g_wmh  [(LAYERS-1) * H_ * 3 * H_], g_wml[(LAYERS-1) * H_ * 3 * H_];
// graph / mixprop
__device__ float g_m1 [C_ * H_];
__device__ float g_m2 [C_ * H_];
__device__ float g_adj[C_ * C_];
__device__ __align__(256) __half g_ho [(size_t)BS * C_ * NCLS * 3 * H_];   // A: mixprop concat
__device__ __align__(256) float  g_mpo[(size_t)BS * C_ * NCLS * H_];
__device__ __align__(256) float  g_z  [(size_t)BS * C_ * NCLS * H_];
__device__ float g_d1 [BS * H_];

// ================= HMMA GEMM (fp16x2, 128x128 tile, 3-stage, 1 sync/chunk) =
// C[M,N] = A[M,K] @ B[N,K]^T + bias.
// mode 0: fp32 out; mode 1: relu + fp16 single; mode 2: fp16 out (Cf cast).
// grid = (N/128, M/128), 256 threads. M,N %128 == 0, K %32 == 0, K/32 >= 2.
#define ASTR    40                        // fp16 row pitch (80B) — conflict-free
#define TILE_B  (128 * ASTR * 2)          // 10240 bytes per tile buffer
#define STAGE_B (3 * TILE_B)              // A, Bh, Bl = 30720
#define NSTAGE  3
#define SMEM_GEMM_BYTES (NSTAGE * STAGE_B)  // 92160 -> 2 CTAs/SM
#define OFF_A   0
#define OFF_BH  TILE_B
#define OFF_BL  (2 * TILE_B)

__global__ __launch_bounds__(256) void gemm_h2_kernel(
    const __half* __restrict__ A,
    const __half* __restrict__ Bh, const __half* __restrict__ Bl,
    const float* __restrict__ bias,
    float* __restrict__ Cf, __half* __restrict__ Ch,
    int M, int N, int K, int mode)
{
    extern __shared__ char smem[];
    uint32_t sb = smem_u32(smem);
    int tid = threadIdx.x;
    int lane = tid & 31;
    int w = tid >> 5;
    int wm = w >> 2;            // 0..1
    int wn = w & 3;             // 0..3
    int m0 = blockIdx.y * 128, n0 = blockIdx.x * 128;

    float acc[4][4][4];
    #pragma unroll
    for (int i = 0; i < 4; i++)
        #pragma unroll
        for (int j = 0; j < 4; j++)
            #pragma unroll
            for (int k = 0; k < 4; k++) acc[i][j][k] = 0.f;

    int nch = K >> 5;

    // ---- stage loader: per tile 128 rows x 32 fp16; 2 x 16B per thread ----
    #define ISSUE_STAGE(cidx, bidx) do {                                         \
        int _kc = (cidx) << 5;                                                   \
        uint32_t _base = sb + (uint32_t)(bidx) * STAGE_B;                        \
        _Pragma("unroll")                                                        \
        for (int _i = 0; _i < 2; _i++) {                                         \
            int _id = tid + _i * 256;                                            \
            int _r = _id >> 2;                                                   \
            int _cc = (_id & 3) << 3;                                            \
            uint32_t _do = (uint32_t)(_r * (ASTR * 2) + _cc * 2);                \
            size_t _ga = (size_t)(m0 + _r) * K + _kc + _cc;                      \
            size_t _gb = (size_t)(n0 + _r) * K + _kc + _cc;                      \
            cp16(_base + OFF_A  + _do, A  + _ga);                                \
            cp16(_base + OFF_BH + _do, Bh + _gb);                                \
            cp16(_base + OFF_BL + _do, Bl + _gb);                                \
        }                                                                        \
        asm volatile("cp.async.commit_group;" ::: "memory");                     \
    } while (0)

    ISSUE_STAGE(0, 0);
    ISSUE_STAGE(1, 1);

    for (int c = 0; c < nch; c++) {
        if (c + 1 < nch) asm volatile("cp.async.wait_group 1;" ::: "memory");
        else             asm volatile("cp.async.wait_group 0;" ::: "memory");
        __syncthreads();
        // issue AFTER the sync: buf (c+2)%3 == buf (c-1)%3, whose readers all
        // passed the barrier above -> no second sync needed per chunk.
        if (c + 2 < nch) ISSUE_STAGE(c + 2, (c + 2) % NSTAGE);

        uint32_t base = sb + (uint32_t)(c % NSTAGE) * STAGE_B;
        #pragma unroll
        for (int ks = 0; ks < 2; ks++) {
            uint32_t ah[4][4], bh[4][2], bl[4][2];
            int arow = wm * 64 + (lane & 15);
            int akc  = ks * 16 + (lane >> 4) * 8;
            #pragma unroll
            for (int mf = 0; mf < 4; mf++) {
                uint32_t off = (uint32_t)(((arow + mf * 16) * ASTR + akc) * 2);
                ldsm4(ah[mf], base + OFF_A + off);
            }
            int brow = wn * 32 + (lane & 7);
            int bkc  = ks * 16 + (((lane & 15) >> 3)) * 8;
            #pragma unroll
            for (int nf = 0; nf < 4; nf++) {
                uint32_t off = (uint32_t)(((brow + nf * 8) * ASTR + bkc) * 2);
                ldsm2(bh[nf], base + OFF_BH + off);
                ldsm2(bl[nf], base + OFF_BL + off);
            }
            #pragma unroll
            for (int mf = 0; mf < 4; mf++)
                #pragma unroll
                for (int nf = 0; nf < 4; nf++) {
                    mma16816h(acc[mf][nf], ah[mf], bh[nf]);
                    mma16816h(acc[mf][nf], ah[mf], bl[nf]);
                }
        }
    }

    // ---- epilogue ----
    int rbase = m0 + wm * 64 + (lane >> 2);
    int cbase = n0 + wn * 32 + (lane & 3) * 2;
    #pragma unroll
    for (int mf = 0; mf < 4; mf++) {
        #pragma unroll
        for (int nf = 0; nf < 4; nf++) {
            int r = rbase + mf * 16;
            int cc = cbase + nf * 8;
            float b0 = bias[cc], b1 = bias[cc + 1];
            float v0 = acc[mf][nf][0] + b0, v1 = acc[mf][nf][1] + b1;
            float v2 = acc[mf][nf][2] + b0, v3 = acc[mf][nf][3] + b1;
            if (mode == 0) {
                *(float2*)(Cf + (size_t)r * N + cc)       = make_float2(v0, v1);
                *(float2*)(Cf + (size_t)(r + 8) * N + cc) = make_float2(v2, v3);
            } else if (mode == 2) {
                __half* Hc = (__half*)Cf;
                *(__half2*)(Hc + (size_t)r * N + cc)       = __floats2half2_rn(v0, v1);
                *(__half2*)(Hc + (size_t)(r + 8) * N + cc) = __floats2half2_rn(v2, v3);
            } else {
                v0 = fmaxf(v0, 0.f); v1 = fmaxf(v1, 0.f);
                v2 = fmaxf(v2, 0.f); v3 = fmaxf(v3, 0.f);
                *(__half2*)(Ch + (size_t)r * N + cc)       = __floats2half2_rn(v0, v1);
                *(__half2*)(Ch + (size_t)(r + 8) * N + cc) = __floats2half2_rn(v2, v3);
            }
        }
    }
}

// ================= misc kernels =================
// merged weight conversion (float4-vectorized, 5 segments) -> fp16 pairs
#define NWQKV (LAYERS * 3 * H_ * H_)
#define NWO   (LAYERS * H_ * H_)
#define NW1   (LAYERS * 4 * H_ * H_)
#define NW2   (LAYERS * 4 * H_ * H_)
#define NWM   ((LAYERS - 1) * H_ * 3 * H_)
#define NCONV ((NWQKV + NWO + NW1 + NW2 + NWM) / 4)

__global__ __launch_bounds__(256) void conv_all_kernel(
    const float* __restrict__ Wqkv, const float* __restrict__ Wo,
    const float* __restrict__ W1,   const float* __restrict__ W2,
    const float* __restrict__ Wm)
{
    int i4 = blockIdx.x * 256 + threadIdx.x;
    if (i4 >= NCONV) return;
    int i = i4 * 4;
    const float* src; __half *hi, *lo; int off;
    if (i < NWQKV) { src = Wqkv; hi = g_wqkvh; lo = g_wqkvl; off = i; }
    else if (i < NWQKV + NWO) { src = Wo; hi = g_woh; lo = g_wol; off = i - NWQKV; }
    else if (i < NWQKV + NWO + NW1) { src = W1; hi = g_w1h; lo = g_w1l; off = i - NWQKV - NWO; }
    else if (i < NWQKV + NWO + NW1 + NW2) { src = W2; hi = g_w2h; lo = g_w2l; off = i - NWQKV - NWO - NW1; }
    else { src = Wm; hi = g_wmh; lo = g_wml; off = i - NWQKV - NWO - NW1 - NW2; }
    float4 v = *(const float4*)(src + off);
    __half h0, l0, h1, l1, h2, l2, h3, l3;
    split_fp16(v.x, h0, l0); split_fp16(v.y, h1, l1);
    split_fp16(v.z, h2, l2); split_fp16(v.w, h3, l3);
    __half2 p0; p0.x = h0; p0.y = h1;
    __half2 p1; p1.x = h2; p1.y = h3;
    __half2 q0; q0.x = l0; q0.y = l1;
    __half2 q1; q1.x = l2; q1.y = l3;
    *(__half2*)(hi + off)     = p0;
    *(__half2*)(hi + off + 2) = p1;
    *(__half2*)(lo + off)     = q0;
    *(__half2*)(lo + off + 2) = q1;
}

__global__ __launch_bounds__(256) void embed_kernel(
    const float* __restrict__ x, const float* __restrict__ Wfc,
    const float* __restrict__ bfc, const float* __restrict__ cls,
    const float* __restrict__ pos)
{
    int row = blockIdx.x;
    int l  = row % L_;
    int bc = row / L_;
    int c  = bc % C_;
    int b  = bc / C_;
    int t  = threadIdx.x;

    __shared__ float xs[IN_];
    float val;
    if (l < T_) {
        if (t < IN_) xs[t] = x[(((size_t)b * T_ + l) * C_ + c) * IN_ + t];
        __syncthreads();
        float s = bfc[t];
        #pragma unroll
        for (int i = 0; i < IN_; i++) s += xs[i] * Wfc[t * IN_ + i];
        val = s;
    } else {
        val = cls[((l - T_) * C_ + c) * H_ + t];
    }
    val += pos[((size_t)l * C_ + c) * H_ + t];
    size_t o = (size_t)row * H_ + t;
    g_h[o]  = val;
    g_hh[o] = __float2half_rn(val);
}

__global__ __launch_bounds__(256) void graph_kernel(
    const float* __restrict__ emb1, const float* __restrict__ emb2,
    const float* __restrict__ Wl1, const float* __restrict__ bl1,
    const float* __restrict__ Wl2, const float* __restrict__ bl2)
{
    int t = threadIdx.x;
    for (int i = 0; i < C_; i++) {
        float s1 = bl1[t], s2 = bl2[t];
        for (int k = 0; k < H_; k++) {
            s1 += emb1[i * H_ + k] * Wl1[t * H_ + k];
            s2 += emb2[i * H_ + k] * Wl2[t * H_ + k];
        }
        g_m1[i * H_ + t] = tanhf(s1);
        g_m2[i * H_ + t] = tanhf(s2);
    }
    __syncthreads();

    __shared__ float adj[C_][C_];
    __shared__ float rsum[C_];
    int v = t >> 4, w = t & 15;
    float s = 0.f;
    for (int j = 0; j < H_; j++)
        s += g_m1[v * H_ + j] * g_m2[w * H_ + j]
           - g_m2[v * H_ + j] * g_m1[w * H_ + j];
    float gv = fmaxf(tanhf(s), 0.f);
    if (v == w) gv += 1.0f;
    adj[v][w] = gv;
    __syncthreads();
    if (t < C_) {
        float r = 0.f;
        for (int k = 0; k < C_; k++) r += adj[t][k];
        rsum[t] = r;
    }
    __syncthreads();
    g_adj[t] = adj[v][w] / rsum[v];
}

// ================= attention (online softmax, fp16 qkv, fp16 out) ==========
__global__ __launch_bounds__(128) void attn_kernel(const __half* __restrict__ qkv)
{
    int bh = blockIdx.x;
    int b = bh >> 3;
    int h = bh & 7;
    __shared__ float4 Ks[L_][8];
    __shared__ float4 Vs[L_][8];
    const __half* base = qkv + (size_t)b * L_ * (3 * H_) + h * DH_;
    for (int idx = threadIdx.x; idx < L_ * 8; idx += 128) {
        int l = idx >> 3, k4 = idx & 7;
        const __half2* kp = (const __half2*)(base + (size_t)l * (3 * H_) + H_     + k4 * 4);
        const __half2* vp = (const __half2*)(base + (size_t)l * (3 * H_) + 2 * H_ + k4 * 4);
        float2 k0 = __half22float2(kp[0]), k1 = __half22float2(kp[1]);
        float2 vv0 = __half22float2(vp[0]), vv1 = __half22float2(vp[1]);
        Ks[l][k4] = make_float4(k0.x, k0.y, k1.x, k1.y);
        Vs[l][k4] = make_float4(vv0.x, vv0.y, vv1.x, vv1.y);
    }
    __syncthreads();

    int i = threadIdx.x;
    if (i < L_) {
        float4 q[8];
        #pragma unroll
        for (int k4 = 0; k4 < 8; k4++) {
            const __half2* qp = (const __half2*)(base + (size_t)i * (3 * H_) + k4 * 4);
            float2 q0 = __half22float2(qp[0]), q1 = __half22float2(qp[1]);
            q[k4] = make_float4(q0.x, q0.y, q1.x, q1.y);
        }

        float m = -1e30f, lsum = 0.f;
        float4 acc[8];
        #pragma unroll
        for (int k4 = 0; k4 < 8; k4++) acc[k4] = make_float4(0.f, 0.f, 0.f, 0.f);

        int jmax = (i >= T_) ? L_ : (i + 1);
        for (int j = 0; j < jmax; j++) {
            float a0 = 0.f, a1 = 0.f, a2 = 0.f, a3 = 0.f;
            #pragma unroll
            for (int k4 = 0; k4 < 8; k4++) {
                float4 kv = Ks[j][k4];
                a0 += q[k4].x * kv.x;
                a1 += q[k4].y * kv.y;
                a2 += q[k4].z * kv.z;
                a3 += q[k4].w * kv.w;
            }
            float s = ((a0 + a1) + (a2 + a3)) * 0.17677669529663687f;
            if (s <= m) {
                float p = __expf(s - m);
                lsum += p;
                #pragma unroll
                for (int k4 = 0; k4 < 8; k4++) {
                    float4 vv = Vs[j][k4];
                    acc[k4].x += p * vv.x;
                    acc[k4].y += p * vv.y;
                    acc[k4].z += p * vv.z;
                    acc[k4].w += p * vv.w;
                }
            } else {
                float sc = __expf(m - s);
                lsum = lsum * sc + 1.f;
                #pragma unroll
                for (int k4 = 0; k4 < 8; k4++) {
                    float4 vv = Vs[j][k4];
                    acc[k4].x = acc[k4].x * sc + vv.x;
                    acc[k4].y = acc[k4].y * sc + vv.y;
                    acc[k4].z = acc[k4].z * sc + vv.z;
                    acc[k4].w = acc[k4].w * sc + vv.w;
                }
                m = s;
            }
        }
        float inv = 1.f / lsum;
        size_t o = ((size_t)b * L_ + i) * H_ + h * DH_;
        #pragma unroll
        for (int k4 = 0; k4 < 8; k4++) {
            *(__half2*)(g_a + o + k4 * 4)     = __floats2half2_rn(acc[k4].x * inv, acc[k4].y * inv);
            *(__half2*)(g_a + o + k4 * 4 + 2) = __floats2half2_rn(acc[k4].z * inv, acc[k4].w * inv);
        }
    }
}

// fused residual-add + LayerNorm; writes fp32 h and fp16 single
__global__ __launch_bounds__(256) void add_ln_kernel(
    const float* __restrict__ xin,
    const float* __restrict__ g, const float* __restrict__ bt)
{
    int row = blockIdx.x, t = threadIdx.x;
    size_t base = (size_t)row * H_;
    float v = g_h[base + t] + xin[base + t];

    __shared__ float ws[8];
    float s = v;
    #pragma unroll
    for (int o = 16; o > 0; o >>= 1) s += __shfl_xor_sync(0xffffffffu, s, o);
    if ((t & 31) == 0) ws[t >> 5] = s;
    __syncthreads();
    float tot = 0.f;
    #pragma unroll
    for (int i = 0; i < 8; i++) tot += ws[i];
    float mean = tot * (1.0f / H_);
    float d = v - mean;
    __syncthreads();

    float q = d * d;
    #pragma unroll
    for (int o = 16; o > 0; o >>= 1) q += __shfl_xor_sync(0xffffffffu, q, o);
    if ((t & 31) == 0) ws[t >> 5] = q;
    __syncthreads();
    float qt = 0.f;
    #pragma unroll
    for (int i = 0; i < 8; i++) qt += ws[i];
    float var = qt * (1.0f / H_);

    float out = d * rsqrtf(var + EPS_) * g[t] + bt[t];
    g_h[base + t]  = out;
    g_hh[base + t] = __float2half_rn(out);
}

// ---------------- fused mixprop (gather + 2 prop depths + fp16 out) --------
__global__ __launch_bounds__(256) void mp_fused_kernel()
{
    __shared__ float s0[C_ * H_];
    __shared__ float s1[C_ * H_];
    __shared__ float adjs[C_ * C_];

    int n = blockIdx.x >> 2;
    int l = blockIdx.x & 3;
    int t = threadIdx.x;
    adjs[t] = g_adj[t];

    #pragma unroll
    for (int w = 0; w < C_; w++) {
        float v = g_h[(((size_t)(n * C_ + w)) * L_ + T_ + l) * H_ + t];
        s0[w * H_ + t] = v;
        size_t r = (size_t)((n * C_ + w) * NCLS + l) * (3 * H_);
        g_ho[r + t] = __float2half_rn(v);
    }
    __syncthreads();

    #pragma unroll
    for (int v = 0; v < C_; v++) {
        float s = 0.f;
        #pragma unroll
        for (int w = 0; w < C_; w++)
            s += adjs[v * C_ + w] * s0[w * H_ + t];
        s1[v * H_ + t] = s;
        size_t r = (size_t)((n * C_ + v) * NCLS + l) * (3 * H_) + H_;
        g_ho[r + t] = __float2half_rn(s);
    }
    __syncthreads();

    #pragma unroll
    for (int v = 0; v < C_; v++) {
        float s = 0.f;
        #pragma unroll
        for (int w = 0; w < C_; w++)
            s += adjs[v * C_ + w] * s1[w * H_ + t];
        size_t r = (size_t)((n * C_ + v) * NCLS + l) * (3 * H_) + 2 * H_;
        g_ho[r + t] = __float2half_rn(s);
    }
}

__global__ __launch_bounds__(256) void mp_scatter_kernel()
{
    int idx = blockIdx.x * 256 + threadIdx.x;
    int o  = idx & 255;
    int r  = idx >> 8;
    int l  = r & 3;
    int nw = r >> 2;
    float v = g_mpo[(size_t)r * H_ + o];
    size_t dst = ((size_t)nw * L_ + T_ + l) * H_ + o;
    g_h[dst]  = v;
    g_hh[dst] = __float2half_rn(v);
}

// ---------------- head ----------------
__global__ __launch_bounds__(256) void tanh_gather_kernel()
{
    int idx = blockIdx.x * 256 + threadIdx.x;
    int hd = idx & 255;
    int r  = idx >> 8;
    int n  = r & 3;
    int c  = (r >> 2) & 15;
    int b  = r >> 6;
    g_z[idx] = tanhf(g_h[(((size_t)(b * C_ + c)) * L_ + T_ + n) * H_ + hd]);
}

__global__ __launch_bounds__(512) void head_gemm_kernel(
    const float* __restrict__ Wd1, const float* __restrict__ bd1)
{
    extern __shared__ float zs[];
    int b = blockIdx.x;
    int tid = threadIdx.x;
    for (int i = tid; i < C_ * NCLS * H_; i += 512)
        zs[i] = g_z[(size_t)b * (C_ * NCLS * H_) + i];
    __syncthreads();
    int wid = tid >> 5, lane = tid & 31;
    for (int o = wid; o < H_; o += 16) {
        const float* w = Wd1 + (size_t)o * (C_ * NCLS * H_);
        float s = 0.f;
        for (int k = lane; k < C_ * NCLS * H_; k += 32)
            s += zs[k] * w[k];
        #pragma unroll
        for (int off = 16; off > 0; off >>= 1)
            s += __shfl_xor_sync(0xffffffffu, s, off);
        if (lane == 0) g_d1[b * H_ + o] = s + bd1[o];
    }
}

__global__ __launch_bounds__(256) void head_kernel(
    const float* __restrict__ Wd2, const float* __restrict__ bd2,
    float* __restrict__ out)
{
    int b = blockIdx.x, t = threadIdx.x;
    float x = g_d1[b * H_ + t];
    float gl = 0.5f * x * (1.0f + erff(x * 0.70710678118654752f));
    float v = gl * Wd2[t];
    #pragma unroll
    for (int o = 16; o > 0; o >>= 1) v += __shfl_xor_sync(0xffffffffu, v, o);
    __shared__ float ws[8];
    if ((t & 31) == 0) ws[t >> 5] = v;
    __syncthreads();
    if (t == 0) {
        float s = 0.f;
        #pragma unroll
        for (int i = 0; i < 8; i++) s += ws[i];
        out[b] = s + bd2[0];
    }
}

// ---------------- host ----------------
static float* dev_ptr(const void* symbol)
{
    void* p = nullptr;
    cudaGetSymbolAddress(&p, symbol);
    return (float*)p;
}
static __half* dev_ptr_h(const void* symbol)
{
    void* p = nullptr;
    cudaGetSymbolAddress(&p, symbol);
    return (__half*)p;
}

extern "C" void kernel_launch(void* const* d_in, const int* in_sizes, int n_in,
                              void* d_out, int out_size)
{
    const float* x        = (const float*)d_in[0];
    const float* Wfc      = (const float*)d_in[3];
    const float* bfc      = (const float*)d_in[4];
    const float* cls_tok  = (const float*)d_in[5];
    const float* pos_emb  = (const float*)d_in[6];
    const float* emb1     = (const float*)d_in[7];
    const float* emb2     = (const float*)d_in[8];
    const float* Wl1      = (const float*)d_in[9];
    const float* bl1      = (const float*)d_in[10];
    const float* Wl2      = (const float*)d_in[11];
    const float* bl2      = (const float*)d_in[12];
    const float* Wqkv     = (const float*)d_in[13];
    const float* bqkv     = (const float*)d_in[14];
    const float* Wo       = (const float*)d_in[15];
    const float* bo       = (const float*)d_in[16];
    const float* W1       = (const float*)d_in[17];
    const float* b1       = (const float*)d_in[18];
    const float* W2       = (const float*)d_in[19];
    const float* b2       = (const float*)d_in[20];
    const float* ln1g     = (const float*)d_in[21];
    const float* ln1b     = (const float*)d_in[22];
    const float* ln2g     = (const float*)d_in[23];
    const float* ln2b     = (const float*)d_in[24];
    const float* Wmlp     = (const float*)d_in[25];
    const float* bmlp     = (const float*)d_in[26];
    const float* Wd1      = (const float*)d_in[27];
    const float* bd1      = (const float*)d_in[28];
    const float* Wd2      = (const float*)d_in[29];
    const float* bd2      = (const float*)d_in[30];
    float* out = (float*)d_out;

    static bool inited = false;
    static float *p_t1, *p_mpo;
    static __half *p_qkv, *p_hh, *p_a, *p_f1, *p_ho;
    static __half *p_wqkvh, *p_wqkvl, *p_woh, *p_wol, *p_w1h, *p_w1l,
                  *p_w2h, *p_w2l, *p_wmh, *p_wml;
    if (!inited) {
        cudaFuncSetAttribute(gemm_h2_kernel,
            cudaFuncAttributeMaxDynamicSharedMemorySize, SMEM_GEMM_BYTES);
        cudaFuncSetAttribute(head_gemm_kernel,
            cudaFuncAttributeMaxDynamicSharedMemorySize, C_ * NCLS * H_ * 4);
        p_t1 = dev_ptr(g_t1); p_mpo = dev_ptr(g_mpo);
        p_qkv = dev_ptr_h(g_qkv);
        p_hh = dev_ptr_h(g_hh); p_a = dev_ptr_h(g_a);
        p_f1 = dev_ptr_h(g_f1); p_ho = dev_ptr_h(g_ho);
        p_wqkvh = dev_ptr_h(g_wqkvh); p_wqkvl = dev_ptr_h(g_wqkvl);
        p_woh = dev_ptr_h(g_woh); p_wol = dev_ptr_h(g_wol);
        p_w1h = dev_ptr_h(g_w1h); p_w1l = dev_ptr_h(g_w1l);
        p_w2h = dev_ptr_h(g_w2h); p_w2l = dev_ptr_h(g_w2l);
        p_wmh = dev_ptr_h(g_wmh); p_wml = dev_ptr_h(g_wml);
        inited = true;
    }

    // launch 0: merged weight conversion
    conv_all_kernel<<<(NCONV + 255) / 256, 256>>>(Wqkv, Wo, W1, W2, Wmlp);
    // launches 1-2
    graph_kernel<<<1, 256>>>(emb1, emb2, Wl1, bl1, Wl2, bl2);
    embed_kernel<<<ROWS, 256>>>(x, Wfc, bfc, cls_tok, pos_emb);

    const int MP_THREADS = BS * C_ * NCLS * H_;   // 1,048,576

    for (int l = 0; l < LAYERS; l++) {
        if (l > 0) {
            mp_fused_kernel<<<BS * NCLS, 256>>>();
            gemm_h2_kernel<<<dim3(2, 32), 256, SMEM_GEMM_BYTES>>>(
                p_ho,
                p_wmh + (size_t)(l - 1) * H_ * 3 * H_, p_wml + (size_t)(l - 1) * H_ * 3 * H_,
                bmlp + (size_t)(l - 1) * H_,
                p_mpo, nullptr,
                BS * C_ * NCLS, H_, 3 * H_, 0);
            mp_scatter_kernel<<<MP_THREADS / 256, 256>>>();
        }

        // QKV projection -> fp16
        gemm_h2_kernel<<<dim3(6, ROWS / 128), 256, SMEM_GEMM_BYTES>>>(
            p_hh,
            p_wqkvh + (size_t)l * 3 * H_ * H_, p_wqkvl + (size_t)l * 3 * H_ * H_,
            bqkv + (size_t)l * 3 * H_,
            (float*)p_qkv, nullptr, ROWS, 3 * H_, H_, 2);

        attn_kernel<<<BP * NH_, 128>>>(p_qkv);

        // output projection -> g_t1
        gemm_h2_kernel<<<dim3(2, ROWS / 128), 256, SMEM_GEMM_BYTES>>>(
            p_a,
            p_woh + (size_t)l * H_ * H_, p_wol + (size_t)l * H_ * H_,
            bo + (size_t)l * H_,
            p_t1, nullptr, ROWS, H_, H_, 0);

        add_ln_kernel<<<ROWS, 256>>>(p_t1, ln1g + l * H_, ln1b + l * H_);

        // FFN
        gemm_h2_kernel<<<dim3(8, ROWS / 128), 256, SMEM_GEMM_BYTES>>>(
            p_hh,
            p_w1h + (size_t)l * 4 * H_ * H_, p_w1l + (size_t)l * 4 * H_ * H_,
            b1 + (size_t)l * 4 * H_,
            nullptr, p_f1, ROWS, 4 * H_, H_, 1);

        gemm_h2_kernel<<<dim3(2, ROWS / 128), 256, SMEM_GEMM_BYTES>>>(
            p_f1,
            p_w2h + (size_t)l * 4 * H_ * H_, p_w2l + (size_t)l * 4 * H_ * H_,
            b2 + (size_t)l * H_,
            p_t1, nullptr, ROWS, H_, 4 * H_, 0);

        add_ln_kernel<<<ROWS, 256>>>(p_t1, ln2g + l * H_, ln2b + l * H_);
    }

    tanh_gather_kernel<<<MP_THREADS / 256, 256>>>();
    head_gemm_kernel<<<BS, 512, C_ * NCLS * H_ * 4>>>(Wd1, bd1);
    head_kernel<<<BS, 256>>>(Wd2, bd2, out);
}

// round 17
// speedup vs baseline: 1.0906x; 1.0557x over previous
#include <cuda_runtime.h>
#include <cuda_bf16.h>
#include <cuda_fp16.h>
#include <math.h>
#include <stdint.h>

// ---------------- model constants ----------------
#define BS    64
#define T_    96
#define C_    16
#define IN_   16
#define H_    256
#define NH_   8
#define DH_   32
#define NCLS  4
#define L_    100          // T + NCLS
#define LAYERS 4
#define BP    (BS * C_)    // 1024 sequences
#define ROWS  (BP * L_)    // 102400 token rows
#define EPS_  1e-5f

// ================= low-level helpers =================
__device__ __forceinline__ uint32_t smem_u32(const void* p) {
    uint32_t a;
    asm("{ .reg .u64 t; cvta.to.shared.u64 t, %1; cvt.u32.u64 %0, t; }"
        : "=r"(a) : "l"(p));
    return a;
}
__device__ __forceinline__ void cp16(uint32_t dst, const void* src) {
    asm volatile("cp.async.cg.shared.global [%0], [%1], 16;" :: "r"(dst), "l"(src) : "memory");
}
__device__ __forceinline__ void ldsm4(uint32_t* r, uint32_t addr) {
    asm volatile("ldmatrix.sync.aligned.m8n8.x4.shared.b16 {%0,%1,%2,%3}, [%4];"
        : "=r"(r[0]), "=r"(r[1]), "=r"(r[2]), "=r"(r[3]) : "r"(addr));
}
__device__ __forceinline__ void ldsm2(uint32_t* r, uint32_t addr) {
    asm volatile("ldmatrix.sync.aligned.m8n8.x2.shared.b16 {%0,%1}, [%2];"
        : "=r"(r[0]), "=r"(r[1]) : "r"(addr));
}
// fp16 MMA, fp32 accumulate
__device__ __forceinline__ void mma16816h(float* d, const uint32_t* a, const uint32_t* b) {
    asm volatile("mma.sync.aligned.m16n8k16.row.col.f32.f16.f16.f32 "
        "{%0,%1,%2,%3}, {%4,%5,%6,%7}, {%8,%9}, {%0,%1,%2,%3};"
        : "+f"(d[0]), "+f"(d[1]), "+f"(d[2]), "+f"(d[3])
        : "r"(a[0]), "r"(a[1]), "r"(a[2]), "r"(a[3]), "r"(b[0]), "r"(b[1]));
}

// ---------------- fp16 split helper ----------------
__device__ __forceinline__ void split_fp16(float v, __half& hi, __half& lo) {
    hi = __float2half_rn(v);
    lo = __float2half_rn(v - __half2float(hi));
}

// ---------------- scratch (device globals) -------------
__device__ __align__(256) float  g_h  [(size_t)ROWS * H_];
__device__ __align__(256) __half g_hh [(size_t)ROWS * H_];          // A: encoder input
__device__ __align__(256) __half g_qkv[(size_t)ROWS * 3 * H_];
__device__ __align__(256) __half g_a  [(size_t)ROWS * H_];          // A: attention out
__device__ __align__(256) float  g_t1 [(size_t)ROWS * H_];
__device__ __align__(256) __half g_f1 [(size_t)ROWS * 4 * H_];      // A: relu out
// weights (fp16 pairs)
__device__ __align__(256) __half g_wqkvh[LAYERS * 3 * H_ * H_], g_wqkvl[LAYERS * 3 * H_ * H_];
__device__ __align__(256) __half g_woh  [LAYERS * H_ * H_],     g_wol  [LAYERS * H_ * H_];
__device__ __align__(256) __half g_w1h  [LAYERS * 4 * H_ * H_], g_w1l  [LAYERS * 4 * H_ * H_];
__device__ __align__(256) __half g_w2h  [LAYERS * 4 * H_ * H_], g_w2l  [LAYERS * 4 * H_ * H_];
__device__ __align__(256) __half g_wmh  [(LAYERS-1) * H_ * 3 * H_], g_wml[(LAYERS-1) * H_ * 3 * H_];
// graph / mixprop
__device__ float g_m1 [C_ * H_];
__device__ float g_m2 [C_ * H_];
__device__ float g_adj[C_ * C_];
__device__ __align__(256) __half g_ho [(size_t)BS * C_ * NCLS * 3 * H_];   // A: mixprop concat
__device__ __align__(256) float  g_mpo[(size_t)BS * C_ * NCLS * H_];
__device__ __align__(256) float  g_z  [(size_t)BS * C_ * NCLS * H_];
__device__ float g_d1 [BS * H_];

// ================= HMMA GEMM (fp16x2, 128x128 tile, 3-stage, 1 sync/chunk) =
// C[M,N] = A[M,K] @ B[N,K]^T + bias.
// mode 0: fp32 out; mode 1: relu + fp16 single; mode 2: fp16 out (Cf cast).
// grid = (N/128, M/128), 256 threads. M,N %128 == 0, K %32 == 0, K/32 >= 2.
#define ASTR    40                        // fp16 row pitch (80B) — conflict-free
#define TILE_B  (128 * ASTR * 2)          // 10240 bytes per tile buffer
#define STAGE_B (3 * TILE_B)              // A, Bh, Bl = 30720
#define NSTAGE  3
#define SMEM_GEMM_BYTES (NSTAGE * STAGE_B)  // 92160 -> 2 CTAs/SM
#define OFF_A   0
#define OFF_BH  TILE_B
#define OFF_BL  (2 * TILE_B)

__global__ __launch_bounds__(256) void gemm_h2_kernel(
    const __half* __restrict__ A,
    const __half* __restrict__ Bh, const __half* __restrict__ Bl,
    const float* __restrict__ bias,
    float* __restrict__ Cf, __half* __restrict__ Ch,
    int M, int N, int K, int mode)
{
    extern __shared__ char smem[];
    uint32_t sb = smem_u32(smem);
    int tid = threadIdx.x;
    int lane = tid & 31;
    int w = tid >> 5;
    int wm = w >> 2;            // 0..1
    int wn = w & 3;             // 0..3
    int m0 = blockIdx.y * 128, n0 = blockIdx.x * 128;

    float acc[4][4][4];
    #pragma unroll
    for (int i = 0; i < 4; i++)
        #pragma unroll
        for (int j = 0; j < 4; j++)
            #pragma unroll
            for (int k = 0; k < 4; k++) acc[i][j][k] = 0.f;

    int nch = K >> 5;

    // ---- stage loader: per tile 128 rows x 32 fp16; 2 x 16B per thread ----
    #define ISSUE_STAGE(cidx, bidx) do {                                         \
        int _kc = (cidx) << 5;                                                   \
        uint32_t _base = sb + (uint32_t)(bidx) * STAGE_B;                        \
        _Pragma("unroll")                                                        \
        for (int _i = 0; _i < 2; _i++) {                                         \
            int _id = tid + _i * 256;                                            \
            int _r = _id >> 2;                                                   \
            int _cc = (_id & 3) << 3;                                            \
            uint32_t _do = (uint32_t)(_r * (ASTR * 2) + _cc * 2);                \
            size_t _ga = (size_t)(m0 + _r) * K + _kc + _cc;                      \
            size_t _gb = (size_t)(n0 + _r) * K + _kc + _cc;                      \
            cp16(_base + OFF_A  + _do, A  + _ga);                                \
            cp16(_base + OFF_BH + _do, Bh + _gb);                                \
            cp16(_base + OFF_BL + _do, Bl + _gb);                                \
        }                                                                        \
        asm volatile("cp.async.commit_group;" ::: "memory");                     \
    } while (0)

    ISSUE_STAGE(0, 0);
    ISSUE_STAGE(1, 1);

    for (int c = 0; c < nch; c++) {
        if (c + 1 < nch) asm volatile("cp.async.wait_group 1;" ::: "memory");
        else             asm volatile("cp.async.wait_group 0;" ::: "memory");
        __syncthreads();
        // issue AFTER the sync: buf (c+2)%3 == buf (c-1)%3, whose readers all
        // passed the barrier above -> no second sync needed per chunk.
        if (c + 2 < nch) ISSUE_STAGE(c + 2, (c + 2) % NSTAGE);

        uint32_t base = sb + (uint32_t)(c % NSTAGE) * STAGE_B;
        #pragma unroll
        for (int ks = 0; ks < 2; ks++) {
            uint32_t ah[4][4], bh[4][2], bl[4][2];
            int arow = wm * 64 + (lane & 15);
            int akc  = ks * 16 + (lane >> 4) * 8;
            #pragma unroll
            for (int mf = 0; mf < 4; mf++) {
                uint32_t off = (uint32_t)(((arow + mf * 16) * ASTR + akc) * 2);
                ldsm4(ah[mf], base + OFF_A + off);
            }
            int brow = wn * 32 + (lane & 7);
            int bkc  = ks * 16 + (((lane & 15) >> 3)) * 8;
            #pragma unroll
            for (int nf = 0; nf < 4; nf++) {
                uint32_t off = (uint32_t)(((brow + nf * 8) * ASTR + bkc) * 2);
                ldsm2(bh[nf], base + OFF_BH + off);
                ldsm2(bl[nf], base + OFF_BL + off);
            }
            #pragma unroll
            for (int mf = 0; mf < 4; mf++)
                #pragma unroll
                for (int nf = 0; nf < 4; nf++) {
                    mma16816h(acc[mf][nf], ah[mf], bh[nf]);
                    mma16816h(acc[mf][nf], ah[mf], bl[nf]);
                }
        }
    }

    // ---- epilogue ----
    int rbase = m0 + wm * 64 + (lane >> 2);
    int cbase = n0 + wn * 32 + (lane & 3) * 2;
    #pragma unroll
    for (int mf = 0; mf < 4; mf++) {
        #pragma unroll
        for (int nf = 0; nf < 4; nf++) {
            int r = rbase + mf * 16;
            int cc = cbase + nf * 8;
            float b0 = bias[cc], b1 = bias[cc + 1];
            float v0 = acc[mf][nf][0] + b0, v1 = acc[mf][nf][1] + b1;
            float v2 = acc[mf][nf][2] + b0, v3 = acc[mf][nf][3] + b1;
            if (mode == 0) {
                *(float2*)(Cf + (size_t)r * N + cc)       = make_float2(v0, v1);
                *(float2*)(Cf + (size_t)(r + 8) * N + cc) = make_float2(v2, v3);
            } else if (mode == 2) {
                __half* Hc = (__half*)Cf;
                *(__half2*)(Hc + (size_t)r * N + cc)       = __floats2half2_rn(v0, v1);
                *(__half2*)(Hc + (size_t)(r + 8) * N + cc) = __floats2half2_rn(v2, v3);
            } else {
                v0 = fmaxf(v0, 0.f); v1 = fmaxf(v1, 0.f);
                v2 = fmaxf(v2, 0.f); v3 = fmaxf(v3, 0.f);
                *(__half2*)(Ch + (size_t)r * N + cc)       = __floats2half2_rn(v0, v1);
                *(__half2*)(Ch + (size_t)(r + 8) * N + cc) = __floats2half2_rn(v2, v3);
            }
        }
    }
}

// ================= misc kernels =================
// merged weight conversion (float4-vectorized, 5 segments) -> fp16 pairs
#define NWQKV (LAYERS * 3 * H_ * H_)
#define NWO   (LAYERS * H_ * H_)
#define NW1   (LAYERS * 4 * H_ * H_)
#define NW2   (LAYERS * 4 * H_ * H_)
#define NWM   ((LAYERS - 1) * H_ * 3 * H_)
#define NCONV ((NWQKV + NWO + NW1 + NW2 + NWM) / 4)

__global__ __launch_bounds__(256) void conv_all_kernel(
    const float* __restrict__ Wqkv, const float* __restrict__ Wo,
    const float* __restrict__ W1,   const float* __restrict__ W2,
    const float* __restrict__ Wm)
{
    int i4 = blockIdx.x * 256 + threadIdx.x;
    if (i4 >= NCONV) return;
    int i = i4 * 4;
    const float* src; __half *hi, *lo; int off;
    if (i < NWQKV) { src = Wqkv; hi = g_wqkvh; lo = g_wqkvl; off = i; }
    else if (i < NWQKV + NWO) { src = Wo; hi = g_woh; lo = g_wol; off = i - NWQKV; }
    else if (i < NWQKV + NWO + NW1) { src = W1; hi = g_w1h; lo = g_w1l; off = i - NWQKV - NWO; }
    else if (i < NWQKV + NWO + NW1 + NW2) { src = W2; hi = g_w2h; lo = g_w2l; off = i - NWQKV - NWO - NW1; }
    else { src = Wm; hi = g_wmh; lo = g_wml; off = i - NWQKV - NWO - NW1 - NW2; }
    float4 v = *(const float4*)(src + off);
    __half h0, l0, h1, l1, h2, l2, h3, l3;
    split_fp16(v.x, h0, l0); split_fp16(v.y, h1, l1);
    split_fp16(v.z, h2, l2); split_fp16(v.w, h3, l3);
    __half2 p0; p0.x = h0; p0.y = h1;
    __half2 p1; p1.x = h2; p1.y = h3;
    __half2 q0; q0.x = l0; q0.y = l1;
    __half2 q1; q1.x = l2; q1.y = l3;
    *(__half2*)(hi + off)     = p0;
    *(__half2*)(hi + off + 2) = p1;
    *(__half2*)(lo + off)     = q0;
    *(__half2*)(lo + off + 2) = q1;
}

__global__ __launch_bounds__(256) void embed_kernel(
    const float* __restrict__ x, const float* __restrict__ Wfc,
    const float* __restrict__ bfc, const float* __restrict__ cls,
    const float* __restrict__ pos)
{
    int row = blockIdx.x;
    int l  = row % L_;
    int bc = row / L_;
    int c  = bc % C_;
    int b  = bc / C_;
    int t  = threadIdx.x;

    __shared__ float xs[IN_];
    float val;
    if (l < T_) {
        if (t < IN_) xs[t] = x[(((size_t)b * T_ + l) * C_ + c) * IN_ + t];
        __syncthreads();
        float s = bfc[t];
        #pragma unroll
        for (int i = 0; i < IN_; i++) s += xs[i] * Wfc[t * IN_ + i];
        val = s;
    } else {
        val = cls[((l - T_) * C_ + c) * H_ + t];
    }
    val += pos[((size_t)l * C_ + c) * H_ + t];
    size_t o = (size_t)row * H_ + t;
    g_h[o]  = val;
    g_hh[o] = __float2half_rn(val);
}

__global__ __launch_bounds__(256) void graph_kernel(
    const float* __restrict__ emb1, const float* __restrict__ emb2,
    const float* __restrict__ Wl1, const float* __restrict__ bl1,
    const float* __restrict__ Wl2, const float* __restrict__ bl2)
{
    int t = threadIdx.x;
    for (int i = 0; i < C_; i++) {
        float s1 = bl1[t], s2 = bl2[t];
        for (int k = 0; k < H_; k++) {
            s1 += emb1[i * H_ + k] * Wl1[t * H_ + k];
            s2 += emb2[i * H_ + k] * Wl2[t * H_ + k];
        }
        g_m1[i * H_ + t] = tanhf(s1);
        g_m2[i * H_ + t] = tanhf(s2);
    }
    __syncthreads();

    __shared__ float adj[C_][C_];
    __shared__ float rsum[C_];
    int v = t >> 4, w = t & 15;
    float s = 0.f;
    for (int j = 0; j < H_; j++)
        s += g_m1[v * H_ + j] * g_m2[w * H_ + j]
           - g_m2[v * H_ + j] * g_m1[w * H_ + j];
    float gv = fmaxf(tanhf(s), 0.f);
    if (v == w) gv += 1.0f;
    adj[v][w] = gv;
    __syncthreads();
    if (t < C_) {
        float r = 0.f;
        for (int k = 0; k < C_; k++) r += adj[t][k];
        rsum[t] = r;
    }
    __syncthreads();
    g_adj[t] = adj[v][w] / rsum[v];
}

// ================= attention (online softmax, fp16 qkv, fp16 out) ==========
__global__ __launch_bounds__(128) void attn_kernel(const __half* __restrict__ qkv)
{
    int bh = blockIdx.x;
    int b = bh >> 3;
    int h = bh & 7;
    __shared__ float4 Ks[L_][8];
    __shared__ float4 Vs[L_][8];
    const __half* base = qkv + (size_t)b * L_ * (3 * H_) + h * DH_;
    for (int idx = threadIdx.x; idx < L_ * 8; idx += 128) {
        int l = idx >> 3, k4 = idx & 7;
        const __half2* kp = (const __half2*)(base + (size_t)l * (3 * H_) + H_     + k4 * 4);
        const __half2* vp = (const __half2*)(base + (size_t)l * (3 * H_) + 2 * H_ + k4 * 4);
        float2 k0 = __half22float2(kp[0]), k1 = __half22float2(kp[1]);
        float2 vv0 = __half22float2(vp[0]), vv1 = __half22float2(vp[1]);
        Ks[l][k4] = make_float4(k0.x, k0.y, k1.x, k1.y);
        Vs[l][k4] = make_float4(vv0.x, vv0.y, vv1.x, vv1.y);
    }
    __syncthreads();

    int i = threadIdx.x;
    if (i < L_) {
        float4 q[8];
        #pragma unroll
        for (int k4 = 0; k4 < 8; k4++) {
            const __half2* qp = (const __half2*)(base + (size_t)i * (3 * H_) + k4 * 4);
            float2 q0 = __half22float2(qp[0]), q1 = __half22float2(qp[1]);
            q[k4] = make_float4(q0.x, q0.y, q1.x, q1.y);
        }

        float m = -1e30f, lsum = 0.f;
        float4 acc[8];
        #pragma unroll
        for (int k4 = 0; k4 < 8; k4++) acc[k4] = make_float4(0.f, 0.f, 0.f, 0.f);

        int jmax = (i >= T_) ? L_ : (i + 1);
        for (int j = 0; j < jmax; j++) {
            float a0 = 0.f, a1 = 0.f, a2 = 0.f, a3 = 0.f;
            #pragma unroll
            for (int k4 = 0; k4 < 8; k4++) {
                float4 kv = Ks[j][k4];
                a0 += q[k4].x * kv.x;
                a1 += q[k4].y * kv.y;
                a2 += q[k4].z * kv.z;
                a3 += q[k4].w * kv.w;
            }
            float s = ((a0 + a1) + (a2 + a3)) * 0.17677669529663687f;
            if (s <= m) {
                float p = __expf(s - m);
                lsum += p;
                #pragma unroll
                for (int k4 = 0; k4 < 8; k4++) {
                    float4 vv = Vs[j][k4];
                    acc[k4].x += p * vv.x;
                    acc[k4].y += p * vv.y;
                    acc[k4].z += p * vv.z;
                    acc[k4].w += p * vv.w;
                }
            } else {
                float sc = __expf(m - s);
                lsum = lsum * sc + 1.f;
                #pragma unroll
                for (int k4 = 0; k4 < 8; k4++) {
                    float4 vv = Vs[j][k4];
                    acc[k4].x = acc[k4].x * sc + vv.x;
                    acc[k4].y = acc[k4].y * sc + vv.y;
                    acc[k4].z = acc[k4].z * sc + vv.z;
                    acc[k4].w = acc[k4].w * sc + vv.w;
                }
                m = s;
            }
        }
        float inv = 1.f / lsum;
        size_t o = ((size_t)b * L_ + i) * H_ + h * DH_;
        #pragma unroll
        for (int k4 = 0; k4 < 8; k4++) {
            *(__half2*)(g_a + o + k4 * 4)     = __floats2half2_rn(acc[k4].x * inv, acc[k4].y * inv);
            *(__half2*)(g_a + o + k4 * 4 + 2) = __floats2half2_rn(acc[k4].z * inv, acc[k4].w * inv);
        }
    }
}

// ===== fused residual-add + LayerNorm: warp per row, float4, no barriers ===
// grid = ROWS/8 blocks of 256 threads (8 warps, 1 row each).
__global__ __launch_bounds__(256) void add_ln_kernel(
    const float* __restrict__ xin,
    const float* __restrict__ g, const float* __restrict__ bt)
{
    int warp = threadIdx.x >> 5, lane = threadIdx.x & 31;
    int row = blockIdx.x * 8 + warp;
    size_t base = (size_t)row * H_ + lane * 8;
    int cb = lane * 8;

    float4 h0 = *(const float4*)(g_h + base);
    float4 h1 = *(const float4*)(g_h + base + 4);
    float4 x0 = *(const float4*)(xin + base);
    float4 x1 = *(const float4*)(xin + base + 4);
    float v[8];
    v[0] = h0.x + x0.x; v[1] = h0.y + x0.y; v[2] = h0.z + x0.z; v[3] = h0.w + x0.w;
    v[4] = h1.x + x1.x; v[5] = h1.y + x1.y; v[6] = h1.z + x1.z; v[7] = h1.w + x1.w;

    float s = ((v[0] + v[1]) + (v[2] + v[3])) + ((v[4] + v[5]) + (v[6] + v[7]));
    #pragma unroll
    for (int o = 16; o > 0; o >>= 1) s += __shfl_xor_sync(0xffffffffu, s, o);
    float mean = s * (1.0f / H_);

    float q = 0.f;
    #pragma unroll
    for (int i = 0; i < 8; i++) { v[i] -= mean; q += v[i] * v[i]; }
    #pragma unroll
    for (int o = 16; o > 0; o >>= 1) q += __shfl_xor_sync(0xffffffffu, q, o);
    float rs = rsqrtf(q * (1.0f / H_) + EPS_);

    float4 g0 = *(const float4*)(g + cb);
    float4 g1 = *(const float4*)(g + cb + 4);
    float4 b0 = *(const float4*)(bt + cb);
    float4 b1 = *(const float4*)(bt + cb + 4);
    float o_[8];
    o_[0] = v[0] * rs * g0.x + b0.x; o_[1] = v[1] * rs * g0.y + b0.y;
    o_[2] = v[2] * rs * g0.z + b0.z; o_[3] = v[3] * rs * g0.w + b0.w;
    o_[4] = v[4] * rs * g1.x + b1.x; o_[5] = v[5] * rs * g1.y + b1.y;
    o_[6] = v[6] * rs * g1.z + b1.z; o_[7] = v[7] * rs * g1.w + b1.w;

    *(float4*)(g_h + base)     = make_float4(o_[0], o_[1], o_[2], o_[3]);
    *(float4*)(g_h + base + 4) = make_float4(o_[4], o_[5], o_[6], o_[7]);

    union { uint4 u; __half2 h[4]; } pk;
    pk.h[0] = __floats2half2_rn(o_[0], o_[1]);
    pk.h[1] = __floats2half2_rn(o_[2], o_[3]);
    pk.h[2] = __floats2half2_rn(o_[4], o_[5]);
    pk.h[3] = __floats2half2_rn(o_[6], o_[7]);
    *(uint4*)(g_hh + base) = pk.u;
}

// ---------------- fused mixprop (gather + 2 prop depths + fp16 out) --------
__global__ __launch_bounds__(256) void mp_fused_kernel()
{
    __shared__ float s0[C_ * H_];
    __shared__ float s1[C_ * H_];
    __shared__ float adjs[C_ * C_];

    int n = blockIdx.x >> 2;
    int l = blockIdx.x & 3;
    int t = threadIdx.x;
    adjs[t] = g_adj[t];

    #pragma unroll
    for (int w = 0; w < C_; w++) {
        float v = g_h[(((size_t)(n * C_ + w)) * L_ + T_ + l) * H_ + t];
        s0[w * H_ + t] = v;
        size_t r = (size_t)((n * C_ + w) * NCLS + l) * (3 * H_);
        g_ho[r + t] = __float2half_rn(v);
    }
    __syncthreads();

    #pragma unroll
    for (int v = 0; v < C_; v++) {
        float s = 0.f;
        #pragma unroll
        for (int w = 0; w < C_; w++)
            s += adjs[v * C_ + w] * s0[w * H_ + t];
        s1[v * H_ + t] = s;
        size_t r = (size_t)((n * C_ + v) * NCLS + l) * (3 * H_) + H_;
        g_ho[r + t] = __float2half_rn(s);
    }
    __syncthreads();

    #pragma unroll
    for (int v = 0; v < C_; v++) {
        float s = 0.f;
        #pragma unroll
        for (int w = 0; w < C_; w++)
            s += adjs[v * C_ + w] * s1[w * H_ + t];
        size_t r = (size_t)((n * C_ + v) * NCLS + l) * (3 * H_) + 2 * H_;
        g_ho[r + t] = __float2half_rn(s);
    }
}

__global__ __launch_bounds__(256) void mp_scatter_kernel()
{
    int idx = blockIdx.x * 256 + threadIdx.x;
    int o  = idx & 255;
    int r  = idx >> 8;
    int l  = r & 3;
    int nw = r >> 2;
    float v = g_mpo[(size_t)r * H_ + o];
    size_t dst = ((size_t)nw * L_ + T_ + l) * H_ + o;
    g_h[dst]  = v;
    g_hh[dst] = __float2half_rn(v);
}

// ---------------- head ----------------
__global__ __launch_bounds__(256) void tanh_gather_kernel()
{
    int idx = blockIdx.x * 256 + threadIdx.x;
    int hd = idx & 255;
    int r  = idx >> 8;
    int n  = r & 3;
    int c  = (r >> 2) & 15;
    int b  = r >> 6;
    g_z[idx] = tanhf(g_h[(((size_t)(b * C_ + c)) * L_ + T_ + n) * H_ + hd]);
}

__global__ __launch_bounds__(512) void head_gemm_kernel(
    const float* __restrict__ Wd1, const float* __restrict__ bd1)
{
    extern __shared__ float zs[];
    int b = blockIdx.x;
    int tid = threadIdx.x;
    for (int i = tid; i < C_ * NCLS * H_; i += 512)
        zs[i] = g_z[(size_t)b * (C_ * NCLS * H_) + i];
    __syncthreads();
    int wid = tid >> 5, lane = tid & 31;
    for (int o = wid; o < H_; o += 16) {
        const float* w = Wd1 + (size_t)o * (C_ * NCLS * H_);
        float s = 0.f;
        for (int k = lane; k < C_ * NCLS * H_; k += 32)
            s += zs[k] * w[k];
        #pragma unroll
        for (int off = 16; off > 0; off >>= 1)
            s += __shfl_xor_sync(0xffffffffu, s, off);
        if (lane == 0) g_d1[b * H_ + o] = s + bd1[o];
    }
}

__global__ __launch_bounds__(256) void head_kernel(
    const float* __restrict__ Wd2, const float* __restrict__ bd2,
    float* __restrict__ out)
{
    int b = blockIdx.x, t = threadIdx.x;
    float x = g_d1[b * H_ + t];
    float gl = 0.5f * x * (1.0f + erff(x * 0.70710678118654752f));
    float v = gl * Wd2[t];
    #pragma unroll
    for (int o = 16; o > 0; o >>= 1) v += __shfl_xor_sync(0xffffffffu, v, o);
    __shared__ float ws[8];
    if ((t & 31) == 0) ws[t >> 5] = v;
    __syncthreads();
    if (t == 0) {
        float s = 0.f;
        #pragma unroll
        for (int i = 0; i < 8; i++) s += ws[i];
        out[b] = s + bd2[0];
    }
}

// ---------------- host ----------------
static float* dev_ptr(const void* symbol)
{
    void* p = nullptr;
    cudaGetSymbolAddress(&p, symbol);
    return (float*)p;
}
static __half* dev_ptr_h(const void* symbol)
{
    void* p = nullptr;
    cudaGetSymbolAddress(&p, symbol);
    return (__half*)p;
}

extern "C" void kernel_launch(void* const* d_in, const int* in_sizes, int n_in,
                              void* d_out, int out_size)
{
    const float* x        = (const float*)d_in[0];
    const float* Wfc      = (const float*)d_in[3];
    const float* bfc      = (const float*)d_in[4];
    const float* cls_tok  = (const float*)d_in[5];
    const float* pos_emb  = (const float*)d_in[6];
    const float* emb1     = (const float*)d_in[7];
    const float* emb2     = (const float*)d_in[8];
    const float* Wl1      = (const float*)d_in[9];
    const float* bl1      = (const float*)d_in[10];
    const float* Wl2      = (const float*)d_in[11];
    const float* bl2      = (const float*)d_in[12];
    const float* Wqkv     = (const float*)d_in[13];
    const float* bqkv     = (const float*)d_in[14];
    const float* Wo       = (const float*)d_in[15];
    const float* bo       = (const float*)d_in[16];
    const float* W1       = (const float*)d_in[17];
    const float* b1       = (const float*)d_in[18];
    const float* W2       = (const float*)d_in[19];
    const float* b2       = (const float*)d_in[20];
    const float* ln1g     = (const float*)d_in[21];
    const float* ln1b     = (const float*)d_in[22];
    const float* ln2g     = (const float*)d_in[23];
    const float* ln2b     = (const float*)d_in[24];
    const float* Wmlp     = (const float*)d_in[25];
    const float* bmlp     = (const float*)d_in[26];
    const float* Wd1      = (const float*)d_in[27];
    const float* bd1      = (const float*)d_in[28];
    const float* Wd2      = (const float*)d_in[29];
    const float* bd2      = (const float*)d_in[30];
    float* out = (float*)d_out;

    static bool inited = false;
    static float *p_t1, *p_mpo;
    static __half *p_qkv, *p_hh, *p_a, *p_f1, *p_ho;
    static __half *p_wqkvh, *p_wqkvl, *p_woh, *p_wol, *p_w1h, *p_w1l,
                  *p_w2h, *p_w2l, *p_wmh, *p_wml;
    if (!inited) {
        cudaFuncSetAttribute(gemm_h2_kernel,
            cudaFuncAttributeMaxDynamicSharedMemorySize, SMEM_GEMM_BYTES);
        cudaFuncSetAttribute(head_gemm_kernel,
            cudaFuncAttributeMaxDynamicSharedMemorySize, C_ * NCLS * H_ * 4);
        p_t1 = dev_ptr(g_t1); p_mpo = dev_ptr(g_mpo);
        p_qkv = dev_ptr_h(g_qkv);
        p_hh = dev_ptr_h(g_hh); p_a = dev_ptr_h(g_a);
        p_f1 = dev_ptr_h(g_f1); p_ho = dev_ptr_h(g_ho);
        p_wqkvh = dev_ptr_h(g_wqkvh); p_wqkvl = dev_ptr_h(g_wqkvl);
        p_woh = dev_ptr_h(g_woh); p_wol = dev_ptr_h(g_wol);
        p_w1h = dev_ptr_h(g_w1h); p_w1l = dev_ptr_h(g_w1l);
        p_w2h = dev_ptr_h(g_w2h); p_w2l = dev_ptr_h(g_w2l);
        p_wmh = dev_ptr_h(g_wmh); p_wml = dev_ptr_h(g_wml);
        inited = true;
    }

    // launch 0: merged weight conversion
    conv_all_kernel<<<(NCONV + 255) / 256, 256>>>(Wqkv, Wo, W1, W2, Wmlp);
    // launches 1-2
    graph_kernel<<<1, 256>>>(emb1, emb2, Wl1, bl1, Wl2, bl2);
    embed_kernel<<<ROWS, 256>>>(x, Wfc, bfc, cls_tok, pos_emb);

    const int MP_THREADS = BS * C_ * NCLS * H_;   // 1,048,576

    for (int l = 0; l < LAYERS; l++) {
        if (l > 0) {
            mp_fused_kernel<<<BS * NCLS, 256>>>();
            gemm_h2_kernel<<<dim3(2, 32), 256, SMEM_GEMM_BYTES>>>(
                p_ho,
                p_wmh + (size_t)(l - 1) * H_ * 3 * H_, p_wml + (size_t)(l - 1) * H_ * 3 * H_,
                bmlp + (size_t)(l - 1) * H_,
                p_mpo, nullptr,
                BS * C_ * NCLS, H_, 3 * H_, 0);
            mp_scatter_kernel<<<MP_THREADS / 256, 256>>>();
        }

        // QKV projection -> fp16
        gemm_h2_kernel<<<dim3(6, ROWS / 128), 256, SMEM_GEMM_BYTES>>>(
            p_hh,
            p_wqkvh + (size_t)l * 3 * H_ * H_, p_wqkvl + (size_t)l * 3 * H_ * H_,
            bqkv + (size_t)l * 3 * H_,
            (float*)p_qkv, nullptr, ROWS, 3 * H_, H_, 2);

        attn_kernel<<<BP * NH_, 128>>>(p_qkv);

        // output projection -> g_t1
        gemm_h2_kernel<<<dim3(2, ROWS / 128), 256, SMEM_GEMM_BYTES>>>(
            p_a,
            p_woh + (size_t)l * H_ * H_, p_wol + (size_t)l * H_ * H_,
            bo + (size_t)l * H_,
            p_t1, nullptr, ROWS, H_, H_, 0);

        add_ln_kernel<<<ROWS / 8, 256>>>(p_t1, ln1g + l * H_, ln1b + l * H_);

        // FFN
        gemm_h2_kernel<<<dim3(8, ROWS / 128), 256, SMEM_GEMM_BYTES>>>(
            p_hh,
            p_w1h + (size_t)l * 4 * H_ * H_, p_w1l + (size_t)l * 4 * H_ * H_,
            b1 + (size_t)l * 4 * H_,
            nullptr, p_f1, ROWS, 4 * H_, H_, 1);

        gemm_h2_kernel<<<dim3(2, ROWS / 128), 256, SMEM_GEMM_BYTES>>>(
            p_f1,
            p_w2h + (size_t)l * 4 * H_ * H_, p_w2l + (size_t)l * 4 * H_ * H_,
            b2 + (size_t)l * H_,
            p_t1, nullptr, ROWS, H_, 4 * H_, 0);

        add_ln_kernel<<<ROWS / 8, 256>>>(p_t1, ln2g + l * H_, ln2b + l * H_);
    }

    tanh_gather_kernel<<<MP_THREADS / 256, 256>>>();
    head_gemm_kernel<<<BS, 512, C_ * NCLS * H_ * 4>>>(Wd1, bd1);
    head_kernel<<<BS, 256>>>(Wd2, bd2, out);
}